// round 6
// baseline (speedup 1.0000x reference)
#include <cuda_runtime.h>
#include <cstdint>

// Leaky RNN: x_t = 0.9*x_{t-1} + 0.1*(u@Win + tanh(x_{t-1})@Wrec + brec) + q_t
//            z_t = tanh(x_t)@Wout + bout
// T=1024, B=64, NIN=32, N=256, NOUT=16.
//
// Pre : g[t,b,n] = noise + 0.1*(u@Win + brec)  (device scratch)
// A   : 64 CTAs (1/batch), 256 thr, thread owns column gn.
//       Wrec[:,gn]: k in [0,192) packed f32x2 registers (192 regs, NO spill),
//       k in [192,256) packed in dynamic smem (16 x LDS.128 per thread).
// B   : outputs = tanh(states) @ Wout + bout (prefetch-pipelined).

#define T_STEPS 1024
#define B_SZ    64
#define N_IN    32
#define N_HID   256
#define N_OUT   16
#define K_REG   192                    // 96 packed pairs in registers
#define K_SM    64                     // 64 rows in smem (16 ulonglong2/col)

typedef unsigned long long ull;

__device__ float g_buf[T_STEPS * B_SZ * N_HID];

__device__ __forceinline__ void ffma2(ull& acc, ull a, ull b) {
    asm("fma.rn.f32x2 %0, %1, %2, %0;" : "+l"(acc) : "l"(a), "l"(b));
}
__device__ __forceinline__ ull fadd2(ull a, ull b) {
    ull r; asm("add.rn.f32x2 %0, %1, %2;" : "=l"(r) : "l"(a), "l"(b)); return r;
}
__device__ __forceinline__ ull pack2(float lo, float hi) {
    ull r; asm("mov.b64 %0, {%1, %2};" : "=l"(r) : "f"(lo), "f"(hi)); return r;
}
__device__ __forceinline__ float hadd2(ull a) {
    float lo, hi; asm("mov.b64 {%0, %1}, %2;" : "=f"(lo), "=f"(hi) : "l"(a));
    return lo + hi;
}
__device__ __forceinline__ float ftanh(float x) {
    float e = __expf(2.0f * x);
    return 1.0f - __fdividef(2.0f, e + 1.0f);
}

// ---------------- Pre-kernel: g = noise + 0.1*(u@Win + brec) ----------------
__global__ void __launch_bounds__(256, 1)
uproj_kernel(const float* __restrict__ inputs,   // [T*B, NIN]
             const float* __restrict__ noise,    // [T*B, N]
             const float* __restrict__ Win,      // [NIN, N]
             const float* __restrict__ brec)     // [N]
{
    __shared__ float su[8][N_IN];
    const int tid = threadIdx.x;

    float w_in[N_IN];
#pragma unroll
    for (int i = 0; i < N_IN; ++i) w_in[i] = Win[i * N_HID + tid];
    const float br = brec[tid];

    const int row0 = blockIdx.x * 8;
    su[tid >> 5][tid & 31] = inputs[row0 * N_IN + tid];
    __syncthreads();

#pragma unroll
    for (int rr = 0; rr < 8; ++rr) {
        const int row = row0 + rr;
        float acc = br;
#pragma unroll
        for (int i = 0; i < N_IN; ++i) acc = fmaf(su[rr][i], w_in[i], acc);
        g_buf[row * N_HID + tid] = noise[row * N_HID + tid] + 0.1f * acc;
    }
}

// ---------------- Kernel A: the recurrence ----------------
// dynamic smem layout: [0,2KB) r_s[2][256] floats; [2KB, 2KB+64KB) wsm ulonglong2[16][256]
#define SMEM_A_BYTES (2048 + K_SM * N_HID * 4)

__global__ void __launch_bounds__(256, 1)
rnn_step_kernel(const float* __restrict__ x0,     // [B,N]
                const float* __restrict__ Wrec,   // [N,N]
                float* __restrict__ states)       // [T,B,N]
{
    extern __shared__ __align__(16) char smem_dyn[];
    float*      r_s = reinterpret_cast<float*>(smem_dyn);               // [2][256]
    ulonglong2* wsm = reinterpret_cast<ulonglong2*>(smem_dyn + 2048);   // [16][256]

    const int tid = threadIdx.x;
    const int b   = blockIdx.x;
    const int gn  = tid;

    // register-stationary packed weights: w[j] = (Wrec[2j][gn], Wrec[2j+1][gn]), k<192
    ull w[K_REG / 2];
#pragma unroll
    for (int j = 0; j < K_REG / 2; ++j)
        w[j] = pack2(Wrec[(2 * j) * N_HID + gn], Wrec[(2 * j + 1) * N_HID + gn]);

    // smem tail: rows [192,256), 4 consecutive k packed per ulonglong2
    for (int jq = 0; jq < K_SM / 4; ++jq) {
        const int k = K_REG + 4 * jq;
        ulonglong2 v;
        v.x = pack2(Wrec[k * N_HID + gn],       Wrec[(k + 1) * N_HID + gn]);
        v.y = pack2(Wrec[(k + 2) * N_HID + gn], Wrec[(k + 3) * N_HID + gn]);
        wsm[jq * N_HID + gn] = v;
    }

    float x = x0[b * N_HID + gn];
    r_s[gn] = ftanh(x);                 // r_{-1} into buffer 0

    const float* gp = g_buf + b * N_HID + gn;
    float greg = gp[0];
    float* sp = states + b * N_HID + gn;
    __syncthreads();

#pragma unroll 1
    for (int t = 0; t < T_STEPS; ++t) {
        const int p  = t & 1;
        const int nb = p ^ 1;

        const int tq = (t + 1 < T_STEPS) ? (t + 1) : (T_STEPS - 1);
        const float gnext = gp[tq * (B_SZ * N_HID)];   // prefetch under the dot

        const ulonglong2* rp = reinterpret_cast<const ulonglong2*>(&r_s[p * N_HID]);
        ull a0 = 0, a1 = 0, a2 = 0, a3 = 0;

        // ---- register part: k in [0,192): 96 FFMA2, 48 broadcast LDS.128 ----
#pragma unroll
        for (int gq = 0; gq < 24; ++gq) {
            ulonglong2 q0 = rp[2 * gq];
            ulonglong2 q1 = rp[2 * gq + 1];
            ffma2(a0, w[4 * gq + 0], q0.x);
            ffma2(a1, w[4 * gq + 1], q0.y);
            ffma2(a2, w[4 * gq + 2], q1.x);
            ffma2(a3, w[4 * gq + 3], q1.y);
        }

        // ---- smem part: k in [192,256): 16 LDS.128 (weights) + 16 bcast + 32 FFMA2 ----
#pragma unroll
        for (int jq = 0; jq < 16; ++jq) {
            ulonglong2 wv = wsm[jq * N_HID + gn];
            ulonglong2 q  = rp[48 + jq];
            ffma2(a0, wv.x, q.x);
            ffma2(a1, wv.y, q.y);
        }

        const float tot = hadd2(fadd2(fadd2(a0, a1), fadd2(a2, a3)));
        x = 0.9f * x + 0.1f * tot + greg;
        greg = gnext;

        sp[t * (B_SZ * N_HID)] = x;          // fire-and-forget STG
        r_s[nb * N_HID + gn] = ftanh(x);

        __syncthreads();
    }
}

// ---------------- Kernel B: z = tanh(states) @ Wout + bout ----------------
__global__ void __launch_bounds__(256, 1)
rnn_out_kernel(const float* __restrict__ states,  // [T*B, N]
               const float* __restrict__ Wout,    // [N, NOUT]
               const float* __restrict__ bout,    // [NOUT]
               float* __restrict__ outputs)       // [T*B, NOUT]
{
    __shared__ __align__(16) float srow[8][N_HID];

    const int tid  = threadIdx.x;
    const int wid  = tid >> 5;
    const int lane = tid & 31;
    const int o    = lane & 15;
    const int h    = lane >> 4;

    ull w[64];
#pragma unroll
    for (int j = 0; j < 64; ++j) {
        int n = h * 128 + 2 * j;
        w[j] = pack2(Wout[n * N_OUT + o], Wout[(n + 1) * N_OUT + o]);
    }
    const float bo = bout[o];

    const int rows = T_STEPS * B_SZ;
    const int warps_total = (gridDim.x * blockDim.x) >> 5;
    int row = (blockIdx.x * blockDim.x + tid) >> 5;
    if (row >= rows) return;

    const float4* src = reinterpret_cast<const float4*>(states + (size_t)row * N_HID);
    float4 v0 = src[lane];
    float4 v1 = src[32 + lane];

    while (true) {
        const int nrow = row + warps_total;
        float4 n0, n1;
        if (nrow < rows) {
            const float4* nsrc = reinterpret_cast<const float4*>(states + (size_t)nrow * N_HID);
            n0 = nsrc[lane];
            n1 = nsrc[32 + lane];
        }

        v0.x = ftanh(v0.x); v0.y = ftanh(v0.y); v0.z = ftanh(v0.z); v0.w = ftanh(v0.w);
        v1.x = ftanh(v1.x); v1.y = ftanh(v1.y); v1.z = ftanh(v1.z); v1.w = ftanh(v1.w);
        float4* dst = reinterpret_cast<float4*>(&srow[wid][0]);
        dst[lane]      = v0;
        dst[32 + lane] = v1;
        __syncwarp();

        const ulonglong2* rp = reinterpret_cast<const ulonglong2*>(&srow[wid][h << 7]);
        ull a0 = 0, a1 = 0;
#pragma unroll
        for (int gq = 0; gq < 32; ++gq) {
            ulonglong2 q = rp[gq];
            ffma2(a0, w[2 * gq + 0], q.x);
            ffma2(a1, w[2 * gq + 1], q.y);
        }
        float zz = hadd2(fadd2(a0, a1));
        zz += __shfl_xor_sync(0xffffffffu, zz, 16);
        if (h == 0)
            outputs[(size_t)row * N_OUT + o] = zz + bo;
        __syncwarp();

        if (nrow >= rows) break;
        row = nrow; v0 = n0; v1 = n1;
    }
}

extern "C" void kernel_launch(void* const* d_in, const int* in_sizes, int n_in,
                              void* d_out, int out_size) {
    const float* inputs = (const float*)d_in[0];
    const float* noise  = (const float*)d_in[1];
    const float* x0     = (const float*)d_in[2];
    const float* Win    = (const float*)d_in[3];
    const float* Wrec   = (const float*)d_in[4];
    const float* brec   = (const float*)d_in[5];
    const float* Wout   = (const float*)d_in[6];
    const float* bout   = (const float*)d_in[7];

    float* outputs = (float*)d_out;                                  // [T,B,NOUT]
    float* states  = (float*)d_out + (size_t)T_STEPS * B_SZ * N_OUT; // [T,B,N]

    cudaFuncSetAttribute(rnn_step_kernel,
                         cudaFuncAttributeMaxDynamicSharedMemorySize, SMEM_A_BYTES);

    uproj_kernel<<<dim3(T_STEPS * B_SZ / 8), dim3(256)>>>(inputs, noise, Win, brec);
    rnn_step_kernel<<<dim3(B_SZ), dim3(256), SMEM_A_BYTES>>>(x0, Wrec, states);
    rnn_out_kernel<<<dim3(592), dim3(256)>>>(states, Wout, bout, outputs);
}